// round 8
// baseline (speedup 1.0000x reference)
#include <cuda_runtime.h>
#include <cuda_bf16.h>
#include <math.h>
#include <stdint.h>

#define NS 19200   // T*H*W
#define TT 12
#define HH 40
#define WW 40
#define CC 128

// Scratch (device globals)
__device__ float    g_inv[NS];          // per-position inv-norm * sqrt(C)
__device__ uint32_t g_q[NS * 64];       // q rows, bf16x2, pre-scaled by C^-0.5
__device__ uint32_t g_k[NS * 64];       // k rows, bf16x2
__device__ uint32_t g_v[NS * 64];       // v rows, bf16x2
__device__ uint32_t g_att[NS * 64];     // attention output rows, bf16x2

__device__ __forceinline__ void mma_bf16(float* c, const uint32_t* a, const uint32_t* b) {
    asm volatile(
        "mma.sync.aligned.m16n8k16.row.col.f32.bf16.bf16.f32 "
        "{%0,%1,%2,%3}, {%4,%5,%6,%7}, {%8,%9}, {%0,%1,%2,%3};\n"
        : "+f"(c[0]), "+f"(c[1]), "+f"(c[2]), "+f"(c[3])
        : "r"(a[0]), "r"(a[1]), "r"(a[2]), "r"(a[3]), "r"(b[0]), "r"(b[1]));
}

__device__ __forceinline__ uint32_t pack_bf16(float x, float y) {
    uint32_t r;
    asm("cvt.rn.bf16x2.f32 %0, %1, %2;" : "=r"(r) : "f"(y), "f"(x));  // lo=x, hi=y
    return r;
}

// ---------------------------------------------------------------------------
// Kernel 1: per-position inv norm. inv[s] = sqrt(C)/max(||x[:,s]||,eps)
// ---------------------------------------------------------------------------
__global__ void inv_kernel(const float* __restrict__ x) {
    int s4 = (blockIdx.x * blockDim.x + threadIdx.x) * 4;
    if (s4 >= NS) return;
    float4 ss = {0.f, 0.f, 0.f, 0.f};
#pragma unroll 8
    for (int c = 0; c < CC; c++) {
        float4 v = *(const float4*)(x + (size_t)c * NS + s4);
        ss.x = fmaf(v.x, v.x, ss.x);
        ss.y = fmaf(v.y, v.y, ss.y);
        ss.z = fmaf(v.z, v.z, ss.z);
        ss.w = fmaf(v.w, v.w, ss.w);
    }
    const float sC = 11.313708498984761f;  // sqrt(128)
    float4 inv;
    inv.x = sC / fmaxf(sqrtf(ss.x), 1e-12f);
    inv.y = sC / fmaxf(sqrtf(ss.y), 1e-12f);
    inv.z = sC / fmaxf(sqrtf(ss.z), 1e-12f);
    inv.w = sC / fmaxf(sqrtf(ss.w), 1e-12f);
    *(float4*)(g_inv + s4) = inv;
}

// ---------------------------------------------------------------------------
// GEMM geometry: tile 64(M)x64(N), 128 thr = 4 warps (2M x 2N), warp tile
// 32x32, full K=128 resident in bf16 smem, one sync. ~5 CTAs/SM.
// ---------------------------------------------------------------------------
#define LDU 68
#define T_U (64 * LDU)              // one 64-row tile in u32
#define GSMEM (2 * T_U * 4)         // 34816 B
static_assert(GSMEM <= 227 * 1024, "gemm smem");

// Shared mainloop: As/Bs staged, returns acc
struct Frag { float a[2][4][4]; };

__device__ __forceinline__ void gemm_core(const uint32_t* As, const uint32_t* Bs,
                                          int wm, int wn, int g, int tg,
                                          float acc[2][4][4]) {
#pragma unroll
    for (int ks = 0; ks < 8; ks++) {
        int kb = ks * 8;
        uint32_t af[2][4], bf[4][2];
#pragma unroll
        for (int mt = 0; mt < 2; mt++) {
            int m = wm * 32 + mt * 16 + g;
            af[mt][0] = As[m * LDU + kb + tg];
            af[mt][1] = As[(m + 8) * LDU + kb + tg];
            af[mt][2] = As[m * LDU + kb + tg + 4];
            af[mt][3] = As[(m + 8) * LDU + kb + tg + 4];
        }
#pragma unroll
        for (int nt = 0; nt < 4; nt++) {
            int n = wn * 32 + nt * 8 + g;
            bf[nt][0] = Bs[n * LDU + kb + tg];
            bf[nt][1] = Bs[n * LDU + kb + tg + 4];
        }
#pragma unroll
        for (int mt = 0; mt < 2; mt++)
#pragma unroll
            for (int nt = 0; nt < 4; nt++)
                mma_bf16(acc[mt][nt], af[mt], bf[nt]);
    }
}

// Kernel 2: qkv GEMM, fused norm on A-load, bf16 q/k/v outputs.
__global__ void __launch_bounds__(128, 5)
gemm_qkv(const float* __restrict__ x, const float* __restrict__ gamma,
         const float* __restrict__ Bw, const float* __restrict__ bias) {
    extern __shared__ uint32_t su[];
    uint32_t* As = su;
    uint32_t* Bs = su + T_U;

    int tid = threadIdx.x;
    int lane = tid & 31;
    int warp = tid >> 5;
    int wm = warp & 1, wn = warp >> 1;
    int g = lane >> 2, tg = lane & 3;
    int bx = blockIdx.x, by = blockIdx.y;

    // Stage A (64x128 fp32, fused norm): 2048 float4, 16/thread
#pragma unroll
    for (int i = 0; i < 16; i++) {
        int id = tid + i * 128;
        int r = id >> 5, c4 = (id & 31) << 2;
        int row = by * 64 + r;
        int ch = row / 150;
        int s = (row - ch * 150) * 128 + c4;
        float gm = __ldg(&gamma[ch]);
        float4 iv = *(const float4*)(g_inv + s);
        float4 v = *(const float4*)(x + (size_t)row * 128 + c4);
        v.x *= iv.x * gm; v.y *= iv.y * gm; v.z *= iv.z * gm; v.w *= iv.w * gm;
        As[r * LDU + (c4 >> 1)]     = pack_bf16(v.x, v.y);
        As[r * LDU + (c4 >> 1) + 1] = pack_bf16(v.z, v.w);
    }
    // Stage B (64x128 fp32)
    const float* Bbase = Bw + (size_t)bx * 64 * CC;
#pragma unroll
    for (int i = 0; i < 16; i++) {
        int id = tid + i * 128;
        int r = id >> 5, c4 = (id & 31) << 2;
        float4 v = *(const float4*)(Bbase + (size_t)r * CC + c4);
        Bs[r * LDU + (c4 >> 1)]     = pack_bf16(v.x, v.y);
        Bs[r * LDU + (c4 >> 1) + 1] = pack_bf16(v.z, v.w);
    }
    __syncthreads();

    float acc[2][4][4];
#pragma unroll
    for (int i = 0; i < 2; i++)
#pragma unroll
        for (int j = 0; j < 4; j++)
#pragma unroll
            for (int e = 0; e < 4; e++) acc[i][j][e] = 0.f;

    gemm_core(As, Bs, wm, wn, g, tg, acc);

    const float QS = 0.08838834764831845f;  // C^-0.5
#pragma unroll
    for (int nt = 0; nt < 4; nt++) {
        int ng = bx * 64 + wn * 32 + nt * 8 + 2 * tg;  // global col, even
        float2 bb = *(const float2*)(bias + ng);
        int sub = ng >> 7;          // 0=q 1=k 2=v
        int nn = ng & 127;
        uint32_t* dst = (sub == 0) ? g_q : (sub == 1) ? g_k : g_v;
        float sc = (sub == 0) ? QS : 1.0f;
#pragma unroll
        for (int mt = 0; mt < 2; mt++) {
            int row0 = by * 64 + wm * 32 + mt * 16 + g;
            dst[row0 * 64 + (nn >> 1)] =
                pack_bf16((acc[mt][nt][0] + bb.x) * sc, (acc[mt][nt][1] + bb.y) * sc);
            dst[(row0 + 8) * 64 + (nn >> 1)] =
                pack_bf16((acc[mt][nt][2] + bb.x) * sc, (acc[mt][nt][3] + bb.y) * sc);
        }
    }
}

// Kernel 4: proj GEMM (A = g_att bf16 native, +bias +resid -> fp32 out)
__global__ void __launch_bounds__(128, 5)
gemm_proj(const float* __restrict__ Bw, const float* __restrict__ bias,
          const float* __restrict__ resid, float* __restrict__ outArg) {
    extern __shared__ uint32_t su[];
    uint32_t* As = su;
    uint32_t* Bs = su + T_U;

    int tid = threadIdx.x;
    int lane = tid & 31;
    int warp = tid >> 5;
    int wm = warp & 1, wn = warp >> 1;
    int g = lane >> 2, tg = lane & 3;

    // Stage A: bf16 rows straight copy. 64 rows x 16 uint4 = 1024, 8/thread
    const uint32_t* Abase = g_att + (size_t)blockIdx.y * 64 * 64;
#pragma unroll
    for (int i = 0; i < 8; i++) {
        int id = tid + i * 128;
        int r = id >> 4, c = (id & 15) * 4;
        uint4 v = *(const uint4*)(Abase + r * 64 + c);
        *(uint4*)(As + r * LDU + c) = v;
    }
    // Stage B: proj_w fp32 -> bf16
    const float* Bbase = Bw + (size_t)blockIdx.x * 64 * CC;
#pragma unroll
    for (int i = 0; i < 16; i++) {
        int id = tid + i * 128;
        int r = id >> 5, c4 = (id & 31) << 2;
        float4 v = *(const float4*)(Bbase + (size_t)r * CC + c4);
        Bs[r * LDU + (c4 >> 1)]     = pack_bf16(v.x, v.y);
        Bs[r * LDU + (c4 >> 1) + 1] = pack_bf16(v.z, v.w);
    }
    __syncthreads();

    float acc[2][4][4];
#pragma unroll
    for (int i = 0; i < 2; i++)
#pragma unroll
        for (int j = 0; j < 4; j++)
#pragma unroll
            for (int e = 0; e < 4; e++) acc[i][j][e] = 0.f;

    gemm_core(As, Bs, wm, wn, g, tg, acc);

#pragma unroll
    for (int nt = 0; nt < 4; nt++) {
        int n = blockIdx.x * 64 + wn * 32 + nt * 8 + 2 * tg;
        float2 bb = *(const float2*)(bias + n);
#pragma unroll
        for (int mt = 0; mt < 2; mt++) {
            int row0 = blockIdx.y * 64 + wm * 32 + mt * 16 + g;
            float2 r0 = *(const float2*)(resid + (size_t)row0 * 128 + n);
            float2 r1 = *(const float2*)(resid + (size_t)(row0 + 8) * 128 + n);
            float2 o0 = { acc[mt][nt][0] + bb.x + r0.x, acc[mt][nt][1] + bb.y + r0.y };
            float2 o1 = { acc[mt][nt][2] + bb.x + r1.x, acc[mt][nt][3] + bb.y + r1.y };
            *(float2*)(outArg + (size_t)row0 * 128 + n) = o0;
            *(float2*)(outArg + (size_t)(row0 + 8) * 128 + n) = o1;
        }
    }
}

// ---------------------------------------------------------------------------
// Kernel 3: neighborhood attention. 8 positions/CTA (1t x 2h x 4w), union
// 3x4x6 = 72 k/v rows staged bf16x2 (45 KB smem -> 5 CTAs/SM). bf16 output.
// ---------------------------------------------------------------------------
#define KPAD 66   // u32 per bf16 row

__global__ void __launch_bounds__(256)
attn_kernel(const float* __restrict__ rpb) {
    extern __shared__ float sm[];
    float*    qsm   = sm;                               // 8*132 floats
    uint32_t* ksm_u = (uint32_t*)(qsm + 8 * 132);       // 72*KPAD
    uint32_t* vsm_u = ksm_u + 72 * KPAD;                // 72*KPAD
    float*    sc    = (float*)(vsm_u + 72 * KPAD);      // 8*32
    float*    aw    = sc + 256;                         // 8*32
    int*      sl    = (int*)(aw + 256);                 // 8*32

    int tid = threadIdx.x, lane = tid & 31, warp = tid >> 5;
    int w0 = blockIdx.x * 4, h0 = blockIdx.y * 2, t = blockIdx.z;

    int st  = min(max(t  - 1, 0), TT - 3);
    int hlo = min(max(h0 - 1, 0), HH - 3);
    int wlo = min(max(w0 - 1, 0), WW - 3);

    int ph = h0 + (warp >> 2), pw = w0 + (warp & 3);
    int p  = (t * HH + ph) * WW + pw;

    if (lane < 27) {
        int dt = lane / 9, dh = (lane / 3) % 3, dw = lane % 3;
        int sh = min(max(ph - 1, 0), HH - 3);
        int sw = min(max(pw - 1, 0), WW - 3);
        int nt = st + dt, nh = sh + dh, nw = sw + dw;
        sl[warp * 32 + lane] = (dt * 4 + (nh - hlo)) * 6 + (nw - wlo);
        int bt = nt - t + 2, bh = nh - ph + 2, bw = nw - pw + 2;
        sc[warp * 32 + lane] = __ldg(&rpb[(bt * 5 + bh) * 5 + bw]);
    }

    // q: bf16 -> fp32 smem (already scaled)
    {
        uint2 qq = *(const uint2*)(g_q + p * 64 + lane * 2);
        float2 f0 = __bfloat1622float2(*(const __nv_bfloat162*)&qq.x);
        float2 f1 = __bfloat1622float2(*(const __nv_bfloat162*)&qq.y);
        float4 q4 = {f0.x, f0.y, f1.x, f1.y};
        *(float4*)(qsm + warp * 132 + lane * 4) = q4;
    }

    for (int rowid = warp; rowid < 72; rowid += 8) {
        int dt = rowid / 24, rrem = rowid % 24;
        int dh = rrem / 6, dw = rrem % 6;
        int nh = min(hlo + dh, HH - 1);
        int nw = min(wlo + dw, WW - 1);
        int np = ((st + dt) * HH + nh) * WW + nw;
        *(uint2*)(ksm_u + rowid * KPAD + lane * 2) = *(const uint2*)(g_k + np * 64 + lane * 2);
        *(uint2*)(vsm_u + rowid * KPAD + lane * 2) = *(const uint2*)(g_v + np * 64 + lane * 2);
    }
    __syncthreads();

    {
        float4 q4 = *(const float4*)(qsm + warp * 132 + lane * 4);
#pragma unroll
        for (int n = 0; n < 27; n++) {
            int slot = sl[warp * 32 + n];
            uint2 kk = *(const uint2*)(ksm_u + slot * KPAD + lane * 2);
            float2 f0 = __bfloat1622float2(*(const __nv_bfloat162*)&kk.x);
            float2 f1 = __bfloat1622float2(*(const __nv_bfloat162*)&kk.y);
            float d = q4.x * f0.x + q4.y * f0.y + q4.z * f1.x + q4.w * f1.y;
#pragma unroll
            for (int o = 16; o; o >>= 1) d += __shfl_xor_sync(0xffffffffu, d, o);
            if (lane == 0) sc[warp * 32 + n] += d;
        }
    }
    __syncwarp();

    {
        float s = (lane < 27) ? sc[warp * 32 + lane] : -1e30f;
        float m = s;
#pragma unroll
        for (int o = 16; o; o >>= 1) m = fmaxf(m, __shfl_xor_sync(0xffffffffu, m, o));
        float e = (lane < 27) ? __expf(s - m) : 0.f;
        float den = e;
#pragma unroll
        for (int o = 16; o; o >>= 1) den += __shfl_xor_sync(0xffffffffu, den, o);
        aw[warp * 32 + lane] = e / den;
    }
    __syncwarp();

    {
        float4 acc = {0.f, 0.f, 0.f, 0.f};
#pragma unroll
        for (int n = 0; n < 27; n++) {
            float a = aw[warp * 32 + n];
            int slot = sl[warp * 32 + n];
            uint2 vv = *(const uint2*)(vsm_u + slot * KPAD + lane * 2);
            float2 f0 = __bfloat1622float2(*(const __nv_bfloat162*)&vv.x);
            float2 f1 = __bfloat1622float2(*(const __nv_bfloat162*)&vv.y);
            acc.x = fmaf(a, f0.x, acc.x);
            acc.y = fmaf(a, f0.y, acc.y);
            acc.z = fmaf(a, f1.x, acc.z);
            acc.w = fmaf(a, f1.y, acc.w);
        }
        uint2 o = { pack_bf16(acc.x, acc.y), pack_bf16(acc.z, acc.w) };
        *(uint2*)(g_att + p * 64 + lane * 2) = o;
    }
}

static const int ATTN_SMEM = 8 * 132 * 4 + 72 * KPAD * 4 * 2 + 256 * 4 * 3;  // 45312 B
static_assert(8 * 132 * 4 + 72 * KPAD * 4 * 2 + 256 * 4 * 3 <= 227 * 1024, "attn smem");

// ---------------------------------------------------------------------------
extern "C" void kernel_launch(void* const* d_in, const int* in_sizes, int n_in,
                              void* d_out, int out_size) {
    const float* x      = (const float*)d_in[0];
    const float* gamma  = (const float*)d_in[1];
    const float* qkv_w  = (const float*)d_in[2];
    const float* qkv_b  = (const float*)d_in[3];
    const float* rpb    = (const float*)d_in[4];
    const float* proj_w = (const float*)d_in[5];
    const float* proj_b = (const float*)d_in[6];
    float* out = (float*)d_out;

    cudaFuncSetAttribute(attn_kernel, cudaFuncAttributeMaxDynamicSharedMemorySize, ATTN_SMEM);
    cudaFuncSetAttribute(gemm_qkv,  cudaFuncAttributeMaxDynamicSharedMemorySize, GSMEM);
    cudaFuncSetAttribute(gemm_proj, cudaFuncAttributeMaxDynamicSharedMemorySize, GSMEM);

    inv_kernel<<<(NS / 4 + 255) / 256, 256>>>(x);
    gemm_qkv<<<dim3(6, NS / 64), 128, GSMEM>>>(x, gamma, qkv_w, qkv_b);
    attn_kernel<<<dim3(WW / 4, HH / 2, TT), 256, ATTN_SMEM>>>(rpb);
    gemm_proj<<<dim3(2, NS / 64), 128, GSMEM>>>(proj_w, proj_b, x, out);
}